// round 2
// baseline (speedup 1.0000x reference)
#include <cuda_runtime.h>
#include <math.h>

#define BQ   4096
#define NSEG 100
#define DIM  4096
#define HID  128
#define TOPK 10
#define NSLICE 16   // d-slices for segment-side partials

// ---------------- scratch (no allocations allowed) ----------------
__device__ float g_qh[BQ * HID];           // query @ rw1[:D]          (2 MB)
__device__ float g_sh[NSEG * HID];         // seg  @ rw1[D:]
__device__ float g_imp[NSEG];              // importance
__device__ float g_cs[NSEG];               // importance * (0.5 + 0.5*decay^(N-1-pos))
__device__ float g_p1[NSLICE * NSEG * HID];
__device__ float g_p2[NSLICE * NSEG * HID];

__device__ __forceinline__ float gelu_f(float x) {
    return 0.5f * x * (1.0f + erff(x * 0.70710678118654752440f));
}
__device__ __forceinline__ float sigmoid_f(float x) {
    return 1.0f / (1.0f + expf(-x));
}

typedef unsigned long long ull;
__device__ __forceinline__ ull pk2(float lo, float hi) {
    ull r; asm("mov.b64 %0, {%1,%2};" : "=l"(r) : "f"(lo), "f"(hi)); return r;
}
__device__ __forceinline__ void fma2(ull& d, ull a, ull b) {
    asm("fma.rn.f32x2 %0, %1, %2, %0;" : "+l"(d) : "l"(a), "l"(b));
}

// ================= kernel 1a: segment partials =================
// grid (NSLICE, NSEG/10), block 128. Block: 10 segments x 256 d's.
__global__ __launch_bounds__(128) void k1a_part(const float* __restrict__ seg,
                                                const float* __restrict__ iw1,
                                                const float* __restrict__ rw1) {
    int h  = threadIdx.x;
    int d0 = blockIdx.x * 256;
    int n0 = blockIdx.y * 10;
    __shared__ float segs[10][256];
    for (int i = h; i < 2560; i += 128) {
        int n = i >> 8, dd = i & 255;
        segs[n][dd] = seg[(size_t)(n0 + n) * DIM + d0 + dd];
    }
    __syncthreads();
    float a1[10], a2[10];
#pragma unroll
    for (int n = 0; n < 10; n++) { a1[n] = 0.f; a2[n] = 0.f; }
    const float* w1p = iw1 + (size_t)d0 * HID + h;
    const float* w2p = rw1 + (size_t)(DIM + d0) * HID + h;
#pragma unroll 4
    for (int dd = 0; dd < 256; dd++) {
        float w1 = w1p[(size_t)dd * HID];
        float w2 = w2p[(size_t)dd * HID];
#pragma unroll
        for (int n = 0; n < 10; n++) {
            a1[n] = fmaf(segs[n][dd], w1, a1[n]);
            a2[n] = fmaf(segs[n][dd], w2, a2[n]);
        }
    }
    int bx = blockIdx.x;
#pragma unroll
    for (int n = 0; n < 10; n++) {
        g_p1[(bx * NSEG + n0 + n) * HID + h] = a1[n];
        g_p2[(bx * NSEG + n0 + n) * HID + h] = a2[n];
    }
}

// ================= kernel 1b: finalize importance / sh =================
__global__ __launch_bounds__(128) void k1b_fin(const int* __restrict__ positions,
                                               const float* __restrict__ ib1,
                                               const float* __restrict__ iw2,
                                               const float* __restrict__ ib2) {
    int n = blockIdx.x, h = threadIdx.x;
    float s1 = 0.f, s2 = 0.f;
#pragma unroll
    for (int s = 0; s < NSLICE; s++) {
        s1 += g_p1[(s * NSEG + n) * HID + h];
        s2 += g_p2[(s * NSEG + n) * HID + h];
    }
    g_sh[n * HID + h] = s2;
    float t = gelu_f(s1 + ib1[h]) * iw2[h];
#pragma unroll
    for (int off = 16; off >= 1; off >>= 1) t += __shfl_xor_sync(0xffffffffu, t, off);
    __shared__ float red[4];
    if ((h & 31) == 0) red[h >> 5] = t;
    __syncthreads();
    if (h == 0) {
        float tot = red[0] + red[1] + red[2] + red[3] + ib2[0];
        float imp = sigmoid_f(tot);
        g_imp[n] = imp;
        float pf = powf(0.95f, (float)(NSEG - 1 - positions[n]));
        g_cs[n]  = imp * (0.5f + 0.5f * pf);
    }
}

// ================= kernel 2: qh = query @ rw1[:D]  (f32x2 GEMM) =================
// grid 128 (32 rows each), block 256. Thread tile 2 rows x 8 cols. K-chunk 32, ping-pong smem.
__global__ __launch_bounds__(256, 1) void k2_qh(const float* __restrict__ query,
                                                const float* __restrict__ rw1) {
    __shared__ float qs[2][32][33];
    __shared__ float ws[2][32][128];
    int tid = threadIdx.x;
    int m0  = blockIdx.x * 32;
    int tx = tid & 15, ty = tid >> 4;
    int c0 = tx * 8, r0 = ty * 2;

    ull acc[2][4];
#pragma unroll
    for (int i = 0; i < 2; i++)
#pragma unroll
        for (int p = 0; p < 4; p++) acc[i][p] = 0ull;

    float qreg[4], wreg[16];

    auto loadc = [&](int kc) {
#pragma unroll
        for (int j = 0; j < 4; j++) {
            int idx = tid + j * 256;
            qreg[j] = query[(size_t)(m0 + (idx >> 5)) * DIM + kc + (idx & 31)];
        }
#pragma unroll
        for (int j = 0; j < 16; j++) {
            int idx = tid + j * 256;
            wreg[j] = rw1[(size_t)(kc + (idx >> 7)) * HID + (idx & 127)];
        }
    };
    auto stores = [&](int bf) {
#pragma unroll
        for (int j = 0; j < 4; j++) {
            int idx = tid + j * 256;
            qs[bf][idx >> 5][idx & 31] = qreg[j];
        }
#pragma unroll
        for (int j = 0; j < 16; j++) {
            int idx = tid + j * 256;
            ws[bf][idx >> 7][idx & 127] = wreg[j];
        }
    };

    loadc(0);
    for (int ch = 0; ch < 128; ch++) {
        int cur = ch & 1;
        stores(cur);
        __syncthreads();
        if (ch < 127) loadc((ch + 1) * 32);
#pragma unroll
        for (int kk = 0; kk < 32; kk++) {
            float q0 = qs[cur][r0][kk];
            float q1 = qs[cur][r0 + 1][kk];
            ull qq0 = pk2(q0, q0), qq1 = pk2(q1, q1);
            const ull* wp = reinterpret_cast<const ull*>(&ws[cur][kk][c0]);
            ull w0 = wp[0], w1 = wp[1], w2 = wp[2], w3 = wp[3];
            fma2(acc[0][0], qq0, w0); fma2(acc[0][1], qq0, w1);
            fma2(acc[0][2], qq0, w2); fma2(acc[0][3], qq0, w3);
            fma2(acc[1][0], qq1, w0); fma2(acc[1][1], qq1, w1);
            fma2(acc[1][2], qq1, w2); fma2(acc[1][3], qq1, w3);
        }
    }
#pragma unroll
    for (int i = 0; i < 2; i++) {
        float* orow = g_qh + (size_t)(m0 + r0 + i) * HID + c0;
#pragma unroll
        for (int p = 0; p < 4; p++) reinterpret_cast<ull*>(orow)[p] = acc[i][p];
    }
}

// ================= kernel 3: rel + top-k + weighted gather =================
// grid BQ/4, block 128 (4 warps). Block handles 4 queries; warp w owns n = w, w+4, ...
__global__ __launch_bounds__(128) void k3_ctx(const float* __restrict__ query,
                                              const float* __restrict__ seg,
                                              const float* __restrict__ rb1,
                                              const float* __restrict__ rw2,
                                              const float* __restrict__ rb2,
                                              float* __restrict__ out) {
    int tid = threadIdx.x, lane = tid & 31, wrp = tid >> 5;
    int b0 = blockIdx.x * 4;

    __shared__ float s_score[4][NSEG];
    __shared__ float s_w[4][NSEG];
    __shared__ int   s_idx[4][TOPK];
    __shared__ float s_wn[4][TOPK];

    float qb[4][4], rv[4];
#pragma unroll
    for (int j = 0; j < 4; j++) {
        int h = lane + 32 * j;
        rv[j] = rw2[h];
        float rb = rb1[h];
#pragma unroll
        for (int b = 0; b < 4; b++) qb[b][j] = g_qh[(size_t)(b0 + b) * HID + h] + rb;
    }
    float rb2v = rb2[0];

    for (int n = wrp; n < NSEG; n += 4) {
        float sh0 = g_sh[n * HID + lane];
        float sh1 = g_sh[n * HID + 32 + lane];
        float sh2 = g_sh[n * HID + 64 + lane];
        float sh3 = g_sh[n * HID + 96 + lane];
        float s[4];
#pragma unroll
        for (int b = 0; b < 4; b++) {
            s[b] = gelu_f(qb[b][0] + sh0) * rv[0];
            s[b] = fmaf(gelu_f(qb[b][1] + sh1), rv[1], s[b]);
            s[b] = fmaf(gelu_f(qb[b][2] + sh2), rv[2], s[b]);
            s[b] = fmaf(gelu_f(qb[b][3] + sh3), rv[3], s[b]);
        }
#pragma unroll
        for (int off = 16; off >= 1; off >>= 1)
#pragma unroll
            for (int b = 0; b < 4; b++) s[b] += __shfl_xor_sync(0xffffffffu, s[b], off);
        if (lane == 0) {
            float imp = g_imp[n], cs = g_cs[n];
#pragma unroll
            for (int b = 0; b < 4; b++) {
                float rel = sigmoid_f(s[b] + rb2v);
                s_score[b][n] = cs * rel;
                s_w[b][n]     = imp * rel;
            }
        }
    }
    __syncthreads();

    // ---- top-k: warp wrp handles b = wrp. Ties -> lower index (jax top_k). ----
    {
        int b = wrp;
        float v0 = s_score[b][lane];
        float v1 = s_score[b][lane + 32];
        float v2 = s_score[b][lane + 64];
        float v3 = (lane + 96 < NSEG) ? s_score[b][lane + 96] : -INFINITY;
        float wsum = 0.f;
        for (int k = 0; k < TOPK; k++) {
            float bv = v0; int bj = 0;
            if (v1 > bv) { bv = v1; bj = 1; }
            if (v2 > bv) { bv = v2; bj = 2; }
            if (v3 > bv) { bv = v3; bj = 3; }
            int bi = lane + 32 * bj;
#pragma unroll
            for (int off = 16; off >= 1; off >>= 1) {
                float ov = __shfl_xor_sync(0xffffffffu, bv, off);
                int   oi = __shfl_xor_sync(0xffffffffu, bi, off);
                if (ov > bv || (ov == bv && oi < bi)) { bv = ov; bi = oi; }
            }
            if ((bi & 31) == lane) {
                int j = bi >> 5;
                if      (j == 0) v0 = -INFINITY;
                else if (j == 1) v1 = -INFINITY;
                else if (j == 2) v2 = -INFINITY;
                else             v3 = -INFINITY;
            }
            wsum += s_w[b][bi];
            if (lane == 0) s_idx[b][k] = bi;
        }
        __syncwarp();
        if (lane < TOPK) {
            int bi = s_idx[b][lane];
            s_wn[b][lane] = s_w[b][bi] / (wsum + 1e-8f);
        }
    }
    __syncthreads();

    // ---- weighted gather: out = query + sum_k wn[k] * seg[idx[k]] ----
    for (int b = 0; b < 4; b++) {
        int bi = b0 + b;
        const float4* sp[TOPK];
        float wn[TOPK];
#pragma unroll
        for (int k = 0; k < TOPK; k++) {
            sp[k] = reinterpret_cast<const float4*>(seg + (size_t)s_idx[b][k] * DIM);
            wn[k] = s_wn[b][k];
        }
        const float4* q4 = reinterpret_cast<const float4*>(query + (size_t)bi * DIM);
        float4*       o4 = reinterpret_cast<float4*>(out + (size_t)bi * DIM);
        for (int t = tid; t < DIM / 4; t += 128) {
            float4 a = q4[t];
#pragma unroll
            for (int k = 0; k < TOPK; k++) {
                float4 sv = sp[k][t];
                a.x = fmaf(wn[k], sv.x, a.x);
                a.y = fmaf(wn[k], sv.y, a.y);
                a.z = fmaf(wn[k], sv.z, a.z);
                a.w = fmaf(wn[k], sv.w, a.w);
            }
            o4[t] = a;
        }
    }
}

// ================= launch =================
extern "C" void kernel_launch(void* const* d_in, const int* in_sizes, int n_in,
                              void* d_out, int out_size) {
    const float* query     = (const float*)d_in[0];
    const float* seg       = (const float*)d_in[1];
    const int*   positions = (const int*)d_in[2];
    const float* iw1       = (const float*)d_in[3];
    const float* ib1       = (const float*)d_in[4];
    const float* iw2       = (const float*)d_in[5];
    const float* ib2       = (const float*)d_in[6];
    const float* rw1       = (const float*)d_in[7];
    const float* rb1       = (const float*)d_in[8];
    const float* rw2       = (const float*)d_in[9];
    const float* rb2       = (const float*)d_in[10];
    float* out = (float*)d_out;

    dim3 g1(NSLICE, NSEG / 10);
    k1a_part<<<g1, 128>>>(seg, iw1, rw1);
    k1b_fin<<<NSEG, 128>>>(positions, ib1, iw2, ib2);
    k2_qh<<<BQ / 32, 256>>>(query, rw1);
    k3_ctx<<<BQ / 4, 128>>>(query, seg, rb1, rw2, rb2, out);
}

// round 4
// speedup vs baseline: 1.8325x; 1.8325x over previous
#include <cuda_runtime.h>
#include <stdint.h>
#include <math.h>

#define BQ   4096
#define NSEG 100
#define DIM  4096
#define HID  128
#define TOPK 10
#define NSLICE 16
#define KSPLIT 4
#define NB 8          // queries per block in k3

// ---------------- scratch ----------------
__device__ float g_qhp[KSPLIT][BQ * HID];  // qh partials (8 MB)
__device__ float g_sh[NSEG * HID];
__device__ float g_imp[NSEG];
__device__ float g_cs[NSEG];
__device__ float g_p1[NSLICE * NSEG * HID];
__device__ float g_p2[NSLICE * NSEG * HID];

__device__ __forceinline__ float gelu_f(float x) {
    return 0.5f * x * (1.0f + erff(x * 0.70710678118654752440f));
}
__device__ __forceinline__ float sigmoid_f(float x) {
    return 1.0f / (1.0f + expf(-x));
}

typedef unsigned long long ull;
__device__ __forceinline__ ull pk2(float lo, float hi) {
    ull r; asm("mov.b64 %0, {%1,%2};" : "=l"(r) : "f"(lo), "f"(hi)); return r;
}
__device__ __forceinline__ void fma2(ull& d, ull a, ull b) {
    asm("fma.rn.f32x2 %0, %1, %2, %0;" : "+l"(d) : "l"(a), "l"(b));
}
__device__ __forceinline__ void cp16(unsigned int saddr, const void* g) {
    asm volatile("cp.async.cg.shared.global [%0], [%1], 16;" :: "r"(saddr), "l"(g));
}
__device__ __forceinline__ void cp_commit() { asm volatile("cp.async.commit_group;"); }
__device__ __forceinline__ void cp_wait0()  { asm volatile("cp.async.wait_group 0;"); }

// ================= kernel 1a: segment partials =================
__global__ __launch_bounds__(128) void k1a_part(const float* __restrict__ seg,
                                                const float* __restrict__ iw1,
                                                const float* __restrict__ rw1) {
    int h  = threadIdx.x;
    int d0 = blockIdx.x * 256;
    int n0 = blockIdx.y * 10;
    __shared__ float segs[10][256];
    for (int i = h; i < 2560; i += 128) {
        int n = i >> 8, dd = i & 255;
        segs[n][dd] = seg[(size_t)(n0 + n) * DIM + d0 + dd];
    }
    __syncthreads();
    float a1[10], a2[10];
#pragma unroll
    for (int n = 0; n < 10; n++) { a1[n] = 0.f; a2[n] = 0.f; }
    const float* w1p = iw1 + (size_t)d0 * HID + h;
    const float* w2p = rw1 + (size_t)(DIM + d0) * HID + h;
#pragma unroll 4
    for (int dd = 0; dd < 256; dd++) {
        float w1 = w1p[(size_t)dd * HID];
        float w2 = w2p[(size_t)dd * HID];
#pragma unroll
        for (int n = 0; n < 10; n++) {
            a1[n] = fmaf(segs[n][dd], w1, a1[n]);
            a2[n] = fmaf(segs[n][dd], w2, a2[n]);
        }
    }
    int bx = blockIdx.x;
#pragma unroll
    for (int n = 0; n < 10; n++) {
        g_p1[(bx * NSEG + n0 + n) * HID + h] = a1[n];
        g_p2[(bx * NSEG + n0 + n) * HID + h] = a2[n];
    }
}

// ================= kernel 1b: finalize importance / sh =================
__global__ __launch_bounds__(128) void k1b_fin(const int* __restrict__ positions,
                                               const float* __restrict__ ib1,
                                               const float* __restrict__ iw2,
                                               const float* __restrict__ ib2) {
    int n = blockIdx.x, h = threadIdx.x;
    float s1 = 0.f, s2 = 0.f;
#pragma unroll
    for (int s = 0; s < NSLICE; s++) {
        s1 += g_p1[(s * NSEG + n) * HID + h];
        s2 += g_p2[(s * NSEG + n) * HID + h];
    }
    g_sh[n * HID + h] = s2;
    float t = gelu_f(s1 + ib1[h]) * iw2[h];
#pragma unroll
    for (int off = 16; off >= 1; off >>= 1) t += __shfl_xor_sync(0xffffffffu, t, off);
    __shared__ float red[4];
    if ((h & 31) == 0) red[h >> 5] = t;
    __syncthreads();
    if (h == 0) {
        float tot = red[0] + red[1] + red[2] + red[3] + ib2[0];
        float imp = sigmoid_f(tot);
        g_imp[n] = imp;
        float pf = powf(0.95f, (float)(NSEG - 1 - positions[n]));
        g_cs[n]  = imp * (0.5f + 0.5f * pf);
    }
}

// ================= kernel 2: qh partials via f32x2, cp.async pipeline =================
// grid 128 = 32 M-blocks x 4 K-splits. 256 threads. CTA tile 128x128, thread tile 8x8.
__global__ __launch_bounds__(256) void k2_qh(const float* __restrict__ query,
                                             const float* __restrict__ rw1) {
    __shared__ float qs[2][128][32];   // [buf][row][kk]  16 KB/buf
    __shared__ float ws[2][32][128];   // [buf][kk][col]  16 KB/buf

    int tid = threadIdx.x;
    int mb = blockIdx.x & 31;
    int ksp = blockIdx.x >> 5;
    int m0 = mb * 128;
    int kbase = ksp * (DIM / KSPLIT);      // 1024-wide K slice
    int tx = tid & 15, ty = tid >> 4;
    int c0 = tx * 8, r0 = ty * 8;

    ull acc[8][4];
#pragma unroll
    for (int i = 0; i < 8; i++)
#pragma unroll
        for (int p = 0; p < 4; p++) acc[i][p] = 0ull;

    unsigned int qs_b = (unsigned int)__cvta_generic_to_shared(&qs[0][0][0]);
    unsigned int ws_b = (unsigned int)__cvta_generic_to_shared(&ws[0][0][0]);

    auto issue = [&](int buf, int kc) {
        // q: 128 rows x 32 floats, 1024 granules of 16B
#pragma unroll
        for (int j = 0; j < 4; j++) {
            int i = tid + j * 256;
            int row = i >> 3, g = i & 7;
            cp16(qs_b + (unsigned int)buf * 16384u + (unsigned int)(row * 128 + g * 16),
                 query + (size_t)(m0 + row) * DIM + kc + g * 4);
        }
        // w: 32 rows x 128 floats, 1024 granules of 16B
#pragma unroll
        for (int j = 0; j < 4; j++) {
            int i = tid + j * 256;
            int row = i >> 5, g = i & 31;
            cp16(ws_b + (unsigned int)buf * 16384u + (unsigned int)(row * 512 + g * 16),
                 rw1 + (size_t)(kc + row) * HID + g * 4);
        }
        cp_commit();
    };

    issue(0, kbase);
    cp_wait0();
    __syncthreads();

    const int NCH = (DIM / KSPLIT) / 32;  // 32 chunks
    for (int ch = 0; ch < NCH; ch++) {
        int cur = ch & 1;
        if (ch + 1 < NCH) issue(cur ^ 1, kbase + (ch + 1) * 32);

#pragma unroll 8
        for (int kk = 0; kk < 32; kk++) {
            const ull* wp = reinterpret_cast<const ull*>(&ws[cur][kk][c0]);
            ull w0 = wp[0], w1 = wp[1], w2 = wp[2], w3 = wp[3];
#pragma unroll
            for (int i = 0; i < 8; i++) {
                float qf = qs[cur][r0 + i][kk];
                ull qd = pk2(qf, qf);
                fma2(acc[i][0], qd, w0);
                fma2(acc[i][1], qd, w1);
                fma2(acc[i][2], qd, w2);
                fma2(acc[i][3], qd, w3);
            }
        }
        cp_wait0();
        __syncthreads();
    }

    float* dst = g_qhp[ksp];
#pragma unroll
    for (int i = 0; i < 8; i++) {
        ull* gq = reinterpret_cast<ull*>(dst + (size_t)(m0 + r0 + i) * HID + c0);
#pragma unroll
        for (int p = 0; p < 4; p++) gq[p] = acc[i][p];
    }
}

// ================= kernel 3: rel + top-k + weighted gather =================
// grid BQ/NB, block 256 (8 warps). Warp w owns n = w, w+8, ... and top-k for b=w.
__global__ __launch_bounds__(256, 2) void k3_ctx(const float* __restrict__ query,
                                                 const float* __restrict__ seg,
                                                 const float* __restrict__ rb1,
                                                 const float* __restrict__ rw2,
                                                 const float* __restrict__ rb2,
                                                 float* __restrict__ out) {
    int tid = threadIdx.x, lane = tid & 31, wrp = tid >> 5;
    int b0 = blockIdx.x * NB;

    __shared__ float s_score[NB][NSEG];
    __shared__ float s_w[NB][NSEG];
    __shared__ int   s_idx[NB][TOPK];
    __shared__ float s_wn[NB][TOPK];

    float qb[NB][4], rv[4];
#pragma unroll
    for (int j = 0; j < 4; j++) {
        int h = lane + 32 * j;
        rv[j] = rw2[h];
        float rb = rb1[h];
#pragma unroll
        for (int b = 0; b < NB; b++) {
            size_t idx = (size_t)(b0 + b) * HID + h;
            float q = g_qhp[0][idx] + g_qhp[1][idx] + g_qhp[2][idx] + g_qhp[3][idx];
            qb[b][j] = q + rb;
        }
    }
    float rb2v = rb2[0];

    for (int n = wrp; n < NSEG; n += 8) {
        float sh0 = g_sh[n * HID + lane];
        float sh1 = g_sh[n * HID + 32 + lane];
        float sh2 = g_sh[n * HID + 64 + lane];
        float sh3 = g_sh[n * HID + 96 + lane];
        float s[NB];
#pragma unroll
        for (int b = 0; b < NB; b++) {
            s[b] = gelu_f(qb[b][0] + sh0) * rv[0];
            s[b] = fmaf(gelu_f(qb[b][1] + sh1), rv[1], s[b]);
            s[b] = fmaf(gelu_f(qb[b][2] + sh2), rv[2], s[b]);
            s[b] = fmaf(gelu_f(qb[b][3] + sh3), rv[3], s[b]);
        }
#pragma unroll
        for (int off = 16; off >= 1; off >>= 1)
#pragma unroll
            for (int b = 0; b < NB; b++) s[b] += __shfl_xor_sync(0xffffffffu, s[b], off);
        if (lane == 0) {
            float imp = g_imp[n], cs = g_cs[n];
#pragma unroll
            for (int b = 0; b < NB; b++) {
                float rel = sigmoid_f(s[b] + rb2v);
                s_score[b][n] = cs * rel;
                s_w[b][n]     = imp * rel;
            }
        }
    }
    __syncthreads();

    // ---- top-k: warp wrp handles b = wrp. Ties -> lower index. ----
    {
        int b = wrp;
        float v0 = s_score[b][lane];
        float v1 = s_score[b][lane + 32];
        float v2 = s_score[b][lane + 64];
        float v3 = (lane + 96 < NSEG) ? s_score[b][lane + 96] : -INFINITY;
        float wsum = 0.f;
        for (int k = 0; k < TOPK; k++) {
            float bv = v0; int bj = 0;
            if (v1 > bv) { bv = v1; bj = 1; }
            if (v2 > bv) { bv = v2; bj = 2; }
            if (v3 > bv) { bv = v3; bj = 3; }
            int bi = lane + 32 * bj;
#pragma unroll
            for (int off = 16; off >= 1; off >>= 1) {
                float ov = __shfl_xor_sync(0xffffffffu, bv, off);
                int   oi = __shfl_xor_sync(0xffffffffu, bi, off);
                if (ov > bv || (ov == bv && oi < bi)) { bv = ov; bi = oi; }
            }
            if ((bi & 31) == lane) {
                int j = bi >> 5;
                if      (j == 0) v0 = -INFINITY;
                else if (j == 1) v1 = -INFINITY;
                else if (j == 2) v2 = -INFINITY;
                else             v3 = -INFINITY;
            }
            wsum += s_w[b][bi];
            if (lane == 0) s_idx[b][k] = bi;
        }
        __syncwarp();
        if (lane < TOPK) {
            int bi = s_idx[b][lane];
            s_wn[b][lane] = s_w[b][bi] / (wsum + 1e-8f);
        }
    }
    __syncthreads();

    // ---- weighted gather ----
    for (int b = 0; b < NB; b++) {
        int bi = b0 + b;
        const float4* sp[TOPK];
        float wn[TOPK];
#pragma unroll
        for (int k = 0; k < TOPK; k++) {
            sp[k] = reinterpret_cast<const float4*>(seg + (size_t)s_idx[b][k] * DIM);
            wn[k] = s_wn[b][k];
        }
        const float4* q4 = reinterpret_cast<const float4*>(query + (size_t)bi * DIM);
        float4*       o4 = reinterpret_cast<float4*>(out + (size_t)bi * DIM);
        for (int t = tid; t < DIM / 4; t += 256) {
            float4 a = q4[t];
#pragma unroll
            for (int k = 0; k < TOPK; k++) {
                float4 sv = sp[k][t];
                a.x = fmaf(wn[k], sv.x, a.x);
                a.y = fmaf(wn[k], sv.y, a.y);
                a.z = fmaf(wn[k], sv.z, a.z);
                a.w = fmaf(wn[k], sv.w, a.w);
            }
            o4[t] = a;
        }
    }
}

// ================= launch =================
extern "C" void kernel_launch(void* const* d_in, const int* in_sizes, int n_in,
                              void* d_out, int out_size) {
    const float* query     = (const float*)d_in[0];
    const float* seg       = (const float*)d_in[1];
    const int*   positions = (const int*)d_in[2];
    const float* iw1       = (const float*)d_in[3];
    const float* ib1       = (const float*)d_in[4];
    const float* iw2       = (const float*)d_in[5];
    const float* ib2       = (const float*)d_in[6];
    const float* rw1       = (const float*)d_in[7];
    const float* rb1       = (const float*)d_in[8];
    const float* rw2       = (const float*)d_in[9];
    const float* rb2       = (const float*)d_in[10];
    float* out = (float*)d_out;

    dim3 g1(NSLICE, NSEG / 10);
    k1a_part<<<g1, 128>>>(seg, iw1, rw1);
    k1b_fin<<<NSEG, 128>>>(positions, ib1, iw2, ib2);
    k2_qh<<<32 * KSPLIT, 256>>>(query, rw1);
    k3_ctx<<<BQ / NB, 256>>>(query, seg, rb1, rw2, rb2, out);
}

// round 5
// speedup vs baseline: 1.8841x; 1.0282x over previous
#include <cuda_runtime.h>
#include <stdint.h>
#include <math.h>

#define BQ   4096
#define NSEG 100
#define DIM  4096
#define HID  128
#define TOPK 10
#define NSLICE 16
#define KSPLIT 4
#define NB 8          // queries per block in k3

// ---------------- scratch ----------------
__device__ float g_qhp[KSPLIT][BQ * HID];  // qh partials (8 MB)
__device__ float g_sh[NSEG * HID];
__device__ float g_imp[NSEG];
__device__ float g_cs[NSEG];
__device__ float g_p1[NSLICE * NSEG * HID];
__device__ float g_p2[NSLICE * NSEG * HID];

__device__ __forceinline__ float gelu_f(float x) {
    return 0.5f * x * (1.0f + erff(x * 0.70710678118654752440f));
}
__device__ __forceinline__ float sigmoid_f(float x) {
    return 1.0f / (1.0f + expf(-x));
}

typedef unsigned long long ull;
__device__ __forceinline__ ull pk2(float lo, float hi) {
    ull r; asm("mov.b64 %0, {%1,%2};" : "=l"(r) : "f"(lo), "f"(hi)); return r;
}
__device__ __forceinline__ void fma2(ull& d, ull a, ull b) {
    asm("fma.rn.f32x2 %0, %1, %2, %0;" : "+l"(d) : "l"(a), "l"(b));
}
__device__ __forceinline__ void cp16(unsigned int saddr, const void* g) {
    asm volatile("cp.async.cg.shared.global [%0], [%1], 16;" :: "r"(saddr), "l"(g));
}
__device__ __forceinline__ void cp_commit() { asm volatile("cp.async.commit_group;"); }
__device__ __forceinline__ void cp_wait0()  { asm volatile("cp.async.wait_group 0;"); }

// ================= kernel 1a: segment partials =================
__global__ __launch_bounds__(128) void k1a_part(const float* __restrict__ seg,
                                                const float* __restrict__ iw1,
                                                const float* __restrict__ rw1) {
    int h  = threadIdx.x;
    int d0 = blockIdx.x * 256;
    int n0 = blockIdx.y * 10;
    __shared__ float segs[10][256];
    for (int i = h; i < 2560; i += 128) {
        int n = i >> 8, dd = i & 255;
        segs[n][dd] = seg[(size_t)(n0 + n) * DIM + d0 + dd];
    }
    __syncthreads();
    float a1[10], a2[10];
#pragma unroll
    for (int n = 0; n < 10; n++) { a1[n] = 0.f; a2[n] = 0.f; }
    const float* w1p = iw1 + (size_t)d0 * HID + h;
    const float* w2p = rw1 + (size_t)(DIM + d0) * HID + h;
#pragma unroll 4
    for (int dd = 0; dd < 256; dd++) {
        float w1 = w1p[(size_t)dd * HID];
        float w2 = w2p[(size_t)dd * HID];
#pragma unroll
        for (int n = 0; n < 10; n++) {
            a1[n] = fmaf(segs[n][dd], w1, a1[n]);
            a2[n] = fmaf(segs[n][dd], w2, a2[n]);
        }
    }
    int bx = blockIdx.x;
#pragma unroll
    for (int n = 0; n < 10; n++) {
        g_p1[(bx * NSEG + n0 + n) * HID + h] = a1[n];
        g_p2[(bx * NSEG + n0 + n) * HID + h] = a2[n];
    }
}

// ================= kernel 1b: finalize importance / sh =================
__global__ __launch_bounds__(128) void k1b_fin(const int* __restrict__ positions,
                                               const float* __restrict__ ib1,
                                               const float* __restrict__ iw2,
                                               const float* __restrict__ ib2) {
    int n = blockIdx.x, h = threadIdx.x;
    float s1 = 0.f, s2 = 0.f;
#pragma unroll
    for (int s = 0; s < NSLICE; s++) {
        s1 += g_p1[(s * NSEG + n) * HID + h];
        s2 += g_p2[(s * NSEG + n) * HID + h];
    }
    g_sh[n * HID + h] = s2;
    float t = gelu_f(s1 + ib1[h]) * iw2[h];
#pragma unroll
    for (int off = 16; off >= 1; off >>= 1) t += __shfl_xor_sync(0xffffffffu, t, off);
    __shared__ float red[4];
    if ((h & 31) == 0) red[h >> 5] = t;
    __syncthreads();
    if (h == 0) {
        float tot = red[0] + red[1] + red[2] + red[3] + ib2[0];
        float imp = sigmoid_f(tot);
        g_imp[n] = imp;
        float pf = powf(0.95f, (float)(NSEG - 1 - positions[n]));
        g_cs[n]  = imp * (0.5f + 0.5f * pf);
    }
}

// ================= kernel 2: qh partials via f32x2, cp.async pipeline =================
// grid 128 = 32 M-blocks x 4 K-splits. 256 threads. CTA tile 128x128, thread tile 8x8.
__global__ __launch_bounds__(256) void k2_qh(const float* __restrict__ query,
                                             const float* __restrict__ rw1) {
    __shared__ float qs[2][128][32];   // [buf][row][kk]  16 KB/buf
    __shared__ float ws[2][32][128];   // [buf][kk][col]  16 KB/buf

    int tid = threadIdx.x;
    int mb = blockIdx.x & 31;
    int ksp = blockIdx.x >> 5;
    int m0 = mb * 128;
    int kbase = ksp * (DIM / KSPLIT);      // 1024-wide K slice
    int tx = tid & 15, ty = tid >> 4;
    int c0 = tx * 8, r0 = ty * 8;

    ull acc[8][4];
#pragma unroll
    for (int i = 0; i < 8; i++)
#pragma unroll
        for (int p = 0; p < 4; p++) acc[i][p] = 0ull;

    unsigned int qs_b = (unsigned int)__cvta_generic_to_shared(&qs[0][0][0]);
    unsigned int ws_b = (unsigned int)__cvta_generic_to_shared(&ws[0][0][0]);

    auto issue = [&](int buf, int kc) {
        // q: 128 rows x 32 floats, 1024 granules of 16B
#pragma unroll
        for (int j = 0; j < 4; j++) {
            int i = tid + j * 256;
            int row = i >> 3, g = i & 7;
            cp16(qs_b + (unsigned int)buf * 16384u + (unsigned int)(row * 128 + g * 16),
                 query + (size_t)(m0 + row) * DIM + kc + g * 4);
        }
        // w: 32 rows x 128 floats, 1024 granules of 16B
#pragma unroll
        for (int j = 0; j < 4; j++) {
            int i = tid + j * 256;
            int row = i >> 5, g = i & 31;
            cp16(ws_b + (unsigned int)buf * 16384u + (unsigned int)(row * 512 + g * 16),
                 rw1 + (size_t)(kc + row) * HID + g * 4);
        }
        cp_commit();
    };

    issue(0, kbase);
    cp_wait0();
    __syncthreads();

    const int NCH = (DIM / KSPLIT) / 32;  // 32 chunks
    for (int ch = 0; ch < NCH; ch++) {
        int cur = ch & 1;
        if (ch + 1 < NCH) issue(cur ^ 1, kbase + (ch + 1) * 32);

#pragma unroll 8
        for (int kk = 0; kk < 32; kk++) {
            const ull* wp = reinterpret_cast<const ull*>(&ws[cur][kk][c0]);
            ull w0 = wp[0], w1 = wp[1], w2 = wp[2], w3 = wp[3];
#pragma unroll
            for (int i = 0; i < 8; i++) {
                float qf = qs[cur][r0 + i][kk];
                ull qd = pk2(qf, qf);
                fma2(acc[i][0], qd, w0);
                fma2(acc[i][1], qd, w1);
                fma2(acc[i][2], qd, w2);
                fma2(acc[i][3], qd, w3);
            }
        }
        cp_wait0();
        __syncthreads();
    }

    float* dst = g_qhp[ksp];
#pragma unroll
    for (int i = 0; i < 8; i++) {
        ull* gq = reinterpret_cast<ull*>(dst + (size_t)(m0 + r0 + i) * HID + c0);
#pragma unroll
        for (int p = 0; p < 4; p++) gq[p] = acc[i][p];
    }
}

// ================= kernel 3: rel + top-k + weighted gather =================
// grid BQ/NB, block 256 (8 warps). Warp w owns n = w, w+8, ... and top-k for b=w.
__global__ __launch_bounds__(256, 2) void k3_ctx(const float* __restrict__ query,
                                                 const float* __restrict__ seg,
                                                 const float* __restrict__ rb1,
                                                 const float* __restrict__ rw2,
                                                 const float* __restrict__ rb2,
                                                 float* __restrict__ out) {
    int tid = threadIdx.x, lane = tid & 31, wrp = tid >> 5;
    int b0 = blockIdx.x * NB;

    __shared__ float s_score[NB][NSEG];
    __shared__ float s_w[NB][NSEG];
    __shared__ int   s_idx[NB][TOPK];
    __shared__ float s_wn[NB][TOPK];

    float qb[NB][4], rv[4];
#pragma unroll
    for (int j = 0; j < 4; j++) {
        int h = lane + 32 * j;
        rv[j] = rw2[h];
        float rb = rb1[h];
#pragma unroll
        for (int b = 0; b < NB; b++) {
            size_t idx = (size_t)(b0 + b) * HID + h;
            float q = g_qhp[0][idx] + g_qhp[1][idx] + g_qhp[2][idx] + g_qhp[3][idx];
            qb[b][j] = q + rb;
        }
    }
    float rb2v = rb2[0];

    for (int n = wrp; n < NSEG; n += 8) {
        float sh0 = g_sh[n * HID + lane];
        float sh1 = g_sh[n * HID + 32 + lane];
        float sh2 = g_sh[n * HID + 64 + lane];
        float sh3 = g_sh[n * HID + 96 + lane];
        float s[NB];
#pragma unroll
        for (int b = 0; b < NB; b++) {
            s[b] = gelu_f(qb[b][0] + sh0) * rv[0];
            s[b] = fmaf(gelu_f(qb[b][1] + sh1), rv[1], s[b]);
            s[b] = fmaf(gelu_f(qb[b][2] + sh2), rv[2], s[b]);
            s[b] = fmaf(gelu_f(qb[b][3] + sh3), rv[3], s[b]);
        }
#pragma unroll
        for (int off = 16; off >= 1; off >>= 1)
#pragma unroll
            for (int b = 0; b < NB; b++) s[b] += __shfl_xor_sync(0xffffffffu, s[b], off);
        if (lane == 0) {
            float imp = g_imp[n], cs = g_cs[n];
#pragma unroll
            for (int b = 0; b < NB; b++) {
                float rel = sigmoid_f(s[b] + rb2v);
                s_score[b][n] = cs * rel;
                s_w[b][n]     = imp * rel;
            }
        }
    }
    __syncthreads();

    // ---- top-k: warp wrp handles b = wrp. Ties -> lower index. ----
    {
        int b = wrp;
        float v0 = s_score[b][lane];
        float v1 = s_score[b][lane + 32];
        float v2 = s_score[b][lane + 64];
        float v3 = (lane + 96 < NSEG) ? s_score[b][lane + 96] : -INFINITY;
        float wsum = 0.f;
        for (int k = 0; k < TOPK; k++) {
            float bv = v0; int bj = 0;
            if (v1 > bv) { bv = v1; bj = 1; }
            if (v2 > bv) { bv = v2; bj = 2; }
            if (v3 > bv) { bv = v3; bj = 3; }
            int bi = lane + 32 * bj;
#pragma unroll
            for (int off = 16; off >= 1; off >>= 1) {
                float ov = __shfl_xor_sync(0xffffffffu, bv, off);
                int   oi = __shfl_xor_sync(0xffffffffu, bi, off);
                if (ov > bv || (ov == bv && oi < bi)) { bv = ov; bi = oi; }
            }
            if ((bi & 31) == lane) {
                int j = bi >> 5;
                if      (j == 0) v0 = -INFINITY;
                else if (j == 1) v1 = -INFINITY;
                else if (j == 2) v2 = -INFINITY;
                else             v3 = -INFINITY;
            }
            wsum += s_w[b][bi];
            if (lane == 0) s_idx[b][k] = bi;
        }
        __syncwarp();
        if (lane < TOPK) {
            int bi = s_idx[b][lane];
            s_wn[b][lane] = s_w[b][bi] / (wsum + 1e-8f);
        }
    }
    __syncthreads();

    // ---- weighted gather ----
    for (int b = 0; b < NB; b++) {
        int bi = b0 + b;
        const float4* sp[TOPK];
        float wn[TOPK];
#pragma unroll
        for (int k = 0; k < TOPK; k++) {
            sp[k] = reinterpret_cast<const float4*>(seg + (size_t)s_idx[b][k] * DIM);
            wn[k] = s_wn[b][k];
        }
        const float4* q4 = reinterpret_cast<const float4*>(query + (size_t)bi * DIM);
        float4*       o4 = reinterpret_cast<float4*>(out + (size_t)bi * DIM);
        for (int t = tid; t < DIM / 4; t += 256) {
            float4 a = q4[t];
#pragma unroll
            for (int k = 0; k < TOPK; k++) {
                float4 sv = sp[k][t];
                a.x = fmaf(wn[k], sv.x, a.x);
                a.y = fmaf(wn[k], sv.y, a.y);
                a.z = fmaf(wn[k], sv.z, a.z);
                a.w = fmaf(wn[k], sv.w, a.w);
            }
            o4[t] = a;
        }
    }
}

// ================= launch =================
extern "C" void kernel_launch(void* const* d_in, const int* in_sizes, int n_in,
                              void* d_out, int out_size) {
    const float* query     = (const float*)d_in[0];
    const float* seg       = (const float*)d_in[1];
    const int*   positions = (const int*)d_in[2];
    const float* iw1       = (const float*)d_in[3];
    const float* ib1       = (const float*)d_in[4];
    const float* iw2       = (const float*)d_in[5];
    const float* ib2       = (const float*)d_in[6];
    const float* rw1       = (const float*)d_in[7];
    const float* rb1       = (const float*)d_in[8];
    const float* rw2       = (const float*)d_in[9];
    const float* rb2       = (const float*)d_in[10];
    float* out = (float*)d_out;

    dim3 g1(NSLICE, NSEG / 10);
    k1a_part<<<g1, 128>>>(seg, iw1, rw1);
    k1b_fin<<<NSEG, 128>>>(positions, ib1, iw2, ib2);
    k2_qh<<<32 * KSPLIT, 256>>>(query, rw1);
    k3_ctx<<<BQ / NB, 256>>>(query, seg, rb1, rw2, rb2, out);
}